// round 1
// baseline (speedup 1.0000x reference)
#include <cuda_runtime.h>
#include <math.h>

#define SN 3072
#define DIN 512
#define NH 16
#define HD_ 64
#define HDIM 1024   // NH * HD_

// -------- scratch (device globals; no allocations allowed) --------
__device__ float g_qh[NH * SN * HD_];   // [H][N][D]
__device__ float g_kh[NH * SN * HD_];
__device__ float g_vh[NH * SN * HD_];
__device__ float g_vals[SN * HDIM];     // [N][H*D]
__device__ float g_hid[SN * HDIM];

// ============================================================
// Projection GEMM: P = X[M,K] @ W[NC,K]^T + b, scatter to [H][N][D]
// BM=BN=64, BK=16, 256 threads, 4x4 per thread
// ============================================================
template<int K>
__global__ void proj_kernel(const float* __restrict__ X,
                            const float* __restrict__ W,
                            const float* __restrict__ b,
                            float* __restrict__ dst) {
    __shared__ float As[64][17];
    __shared__ float Bs[64][17];
    const int tid = threadIdx.x;
    const int tx = tid & 15, ty = tid >> 4;
    const int row0 = blockIdx.y * 64, col0 = blockIdx.x * 64;
    float acc[4][4] = {};
    for (int k0 = 0; k0 < K; k0 += 16) {
        #pragma unroll
        for (int i = 0; i < 4; i++) {
            int idx = tid + i * 256;
            int r = idx >> 4, c = idx & 15;
            As[r][c] = X[(row0 + r) * K + k0 + c];
            Bs[r][c] = W[(col0 + r) * K + k0 + c];
        }
        __syncthreads();
        #pragma unroll
        for (int kk = 0; kk < 16; kk++) {
            float a[4], bb[4];
            #pragma unroll
            for (int i = 0; i < 4; i++) a[i] = As[ty * 4 + i][kk];
            #pragma unroll
            for (int j = 0; j < 4; j++) bb[j] = Bs[tx * 4 + j][kk];
            #pragma unroll
            for (int i = 0; i < 4; i++)
                #pragma unroll
                for (int j = 0; j < 4; j++)
                    acc[i][j] += a[i] * bb[j];
        }
        __syncthreads();
    }
    #pragma unroll
    for (int i = 0; i < 4; i++) {
        int m = row0 + ty * 4 + i;
        #pragma unroll
        for (int j = 0; j < 4; j++) {
            int c = col0 + tx * 4 + j;
            int h = c >> 6, d = c & 63;
            dst[h * (SN * HD_) + m * HD_ + d] = acc[i][j] + b[c];
        }
    }
}

// ============================================================
// MLP GEMM: out = act(X[M,K] @ W[NC,K]^T + b)   ACT: 0=none, 1=mish
// ============================================================
__device__ __forceinline__ float mish_f(float x) {
    float sp = (x > 20.f) ? x : log1pf(__expf(x));
    return x * tanhf(sp);
}

template<int ACT, int K>
__global__ void gemm_kernel(const float* __restrict__ X,
                            const float* __restrict__ W,
                            const float* __restrict__ b,
                            float* __restrict__ out, int NC) {
    __shared__ float As[64][17];
    __shared__ float Bs[64][17];
    const int tid = threadIdx.x;
    const int tx = tid & 15, ty = tid >> 4;
    const int row0 = blockIdx.y * 64, col0 = blockIdx.x * 64;
    float acc[4][4] = {};
    for (int k0 = 0; k0 < K; k0 += 16) {
        #pragma unroll
        for (int i = 0; i < 4; i++) {
            int idx = tid + i * 256;
            int r = idx >> 4, c = idx & 15;
            As[r][c] = X[(row0 + r) * K + k0 + c];
            Bs[r][c] = W[(col0 + r) * K + k0 + c];
        }
        __syncthreads();
        #pragma unroll
        for (int kk = 0; kk < 16; kk++) {
            float a[4], bb[4];
            #pragma unroll
            for (int i = 0; i < 4; i++) a[i] = As[ty * 4 + i][kk];
            #pragma unroll
            for (int j = 0; j < 4; j++) bb[j] = Bs[tx * 4 + j][kk];
            #pragma unroll
            for (int i = 0; i < 4; i++)
                #pragma unroll
                for (int j = 0; j < 4; j++)
                    acc[i][j] += a[i] * bb[j];
        }
        __syncthreads();
    }
    #pragma unroll
    for (int i = 0; i < 4; i++) {
        int m = row0 + ty * 4 + i;
        #pragma unroll
        for (int j = 0; j < 4; j++) {
            int c = col0 + tx * 4 + j;
            float v = acc[i][j] + b[c];
            if (ACT == 1) v = mish_f(v);
            out[m * NC + c] = v;
        }
    }
}

// ============================================================
// Flash attention: one CTA = (head h, 64-row Q block)
// online softmax over 48 key blocks of 64. fp32 SIMT.
// smem: Qs,Ks,Vs,Ps each 64x65 floats = 66560 B (dynamic)
// ============================================================
#define ATTN_SMEM (4 * 64 * 65 * 4)

__global__ void attn_kernel(const float* __restrict__ bias,
                            const int* __restrict__ mask) {
    extern __shared__ float sm[];
    float* Qs = sm;                 // [64][65]
    float* Ks = Qs + 64 * 65;
    float* Vs = Ks + 64 * 65;
    float* Ps = Vs + 64 * 65;

    const int h = blockIdx.x;
    const int qb = blockIdx.y;
    const int q0 = qb * 64;
    const int tid = threadIdx.x;
    const int tx = tid & 15, ty = tid >> 4;
    const int ty4 = ty * 4;
    const int tx4 = tx * 4;

    const float* qp = g_qh + h * SN * HD_ + q0 * HD_;
    const float* kp = g_kh + h * SN * HD_;
    const float* vp = g_vh + h * SN * HD_;

    // load Q block
    #pragma unroll
    for (int i = 0; i < 16; i++) {
        int idx = tid + i * 256;
        int r = idx >> 6, c = idx & 63;
        Qs[r * 65 + c] = qp[r * HD_ + c];
    }

    float O[4][4] = {};
    float m_run[4], l_run[4];
    #pragma unroll
    for (int i = 0; i < 4; i++) { m_run[i] = -INFINITY; l_run[i] = 0.f; }

    for (int jb = 0; jb < SN / 64; jb++) {
        const int k0 = jb * 64;
        // load K, V blocks
        #pragma unroll
        for (int i = 0; i < 16; i++) {
            int idx = tid + i * 256;
            int r = idx >> 6, c = idx & 63;
            Ks[r * 65 + c] = kp[(k0 + r) * HD_ + c];
            Vs[r * 65 + c] = vp[(k0 + r) * HD_ + c];
        }
        __syncthreads();

        // S = Q K^T
        float s[4][4] = {};
        #pragma unroll 8
        for (int d = 0; d < 64; d++) {
            float a[4], bb[4];
            #pragma unroll
            for (int i = 0; i < 4; i++) a[i] = Qs[(ty4 + i) * 65 + d];
            #pragma unroll
            for (int j = 0; j < 4; j++) bb[j] = Ks[(tx4 + j) * 65 + d];
            #pragma unroll
            for (int i = 0; i < 4; i++)
                #pragma unroll
                for (int j = 0; j < 4; j++)
                    s[i][j] += a[i] * bb[j];
        }

        // scale + bias + mask
        #pragma unroll
        for (int i = 0; i < 4; i++) {
            int gr = q0 + ty4 + i;
            float4 bv = *reinterpret_cast<const float4*>(bias + (size_t)gr * SN + k0 + tx4);
            int4   mv = *reinterpret_cast<const int4*>(mask + (size_t)gr * SN + k0 + tx4);
            s[i][0] = (mv.x == 0) ? -9e15f : (s[i][0] * 0.125f + bv.x);
            s[i][1] = (mv.y == 0) ? -9e15f : (s[i][1] * 0.125f + bv.y);
            s[i][2] = (mv.z == 0) ? -9e15f : (s[i][2] * 0.125f + bv.z);
            s[i][3] = (mv.w == 0) ? -9e15f : (s[i][3] * 0.125f + bv.w);
        }

        // online softmax row update
        #pragma unroll
        for (int i = 0; i < 4; i++) {
            float mloc = fmaxf(fmaxf(s[i][0], s[i][1]), fmaxf(s[i][2], s[i][3]));
            #pragma unroll
            for (int o = 8; o >= 1; o >>= 1)
                mloc = fmaxf(mloc, __shfl_xor_sync(0xffffffffu, mloc, o, 16));
            float m_new = fmaxf(m_run[i], mloc);
            float corr = __expf(m_run[i] - m_new);
            float psum = 0.f;
            #pragma unroll
            for (int j = 0; j < 4; j++) {
                float p = __expf(s[i][j] - m_new);
                Ps[(ty4 + i) * 65 + tx4 + j] = p;
                psum += p;
            }
            #pragma unroll
            for (int o = 8; o >= 1; o >>= 1)
                psum += __shfl_xor_sync(0xffffffffu, psum, o, 16);
            l_run[i] = l_run[i] * corr + psum;
            m_run[i] = m_new;
            #pragma unroll
            for (int j = 0; j < 4; j++) O[i][j] *= corr;
        }
        __syncthreads();

        // O += P V
        #pragma unroll 8
        for (int kc = 0; kc < 64; kc++) {
            float p[4], vv[4];
            #pragma unroll
            for (int i = 0; i < 4; i++) p[i] = Ps[(ty4 + i) * 65 + kc];
            #pragma unroll
            for (int j = 0; j < 4; j++) vv[j] = Vs[kc * 65 + tx4 + j];
            #pragma unroll
            for (int i = 0; i < 4; i++)
                #pragma unroll
                for (int j = 0; j < 4; j++)
                    O[i][j] += p[i] * vv[j];
        }
        __syncthreads();
    }

    // finalize: write vals [N][H*D]
    #pragma unroll
    for (int i = 0; i < 4; i++) {
        float inv = 1.f / l_run[i];
        int gr = q0 + ty4 + i;
        #pragma unroll
        for (int j = 0; j < 4; j++)
            g_vals[gr * HDIM + h * HD_ + tx4 + j] = O[i][j] * inv;
    }
}

// ============================================================
extern "C" void kernel_launch(void* const* d_in, const int* in_sizes, int n_in,
                              void* d_out, int out_size) {
    const float* q    = (const float*)d_in[0];
    const float* k    = (const float*)d_in[1];
    const float* v    = (const float*)d_in[2];
    const float* bias = (const float*)d_in[3];
    const int*   mask = (const int*)d_in[4];
    const float* Wq   = (const float*)d_in[5];
    const float* bq   = (const float*)d_in[6];
    const float* Wk   = (const float*)d_in[7];
    const float* bk   = (const float*)d_in[8];
    const float* Wv   = (const float*)d_in[9];
    const float* bv   = (const float*)d_in[10];
    const float* Wo1  = (const float*)d_in[11];
    const float* bo1  = (const float*)d_in[12];
    const float* Wo2  = (const float*)d_in[13];
    const float* bo2  = (const float*)d_in[14];
    float* out = (float*)d_out;

    float *g_qh_p, *g_kh_p, *g_vh_p, *g_vals_p, *g_hid_p;
    cudaGetSymbolAddress((void**)&g_qh_p,  g_qh);
    cudaGetSymbolAddress((void**)&g_kh_p,  g_kh);
    cudaGetSymbolAddress((void**)&g_vh_p,  g_vh);
    cudaGetSymbolAddress((void**)&g_vals_p, g_vals);
    cudaGetSymbolAddress((void**)&g_hid_p, g_hid);

    cudaFuncSetAttribute(attn_kernel,
        cudaFuncAttributeMaxDynamicSharedMemorySize, ATTN_SMEM);

    dim3 blk(256);

    // 1) projections: [3072,512] @ [1024,512]^T -> split heads
    dim3 gp(HDIM / 64, SN / 64);
    proj_kernel<DIN><<<gp, blk>>>(q, Wq, bq, g_qh_p);
    proj_kernel<DIN><<<gp, blk>>>(k, Wk, bk, g_kh_p);
    proj_kernel<DIN><<<gp, blk>>>(v, Wv, bv, g_vh_p);

    // 2) flash attention
    dim3 ga(NH, SN / 64);
    attn_kernel<<<ga, blk, ATTN_SMEM>>>(bias, mask);

    // 3) MLP: mish(vals @ Wo1^T + bo1) @ Wo2^T + bo2
    dim3 g1(HDIM / 64, SN / 64);
    gemm_kernel<1, HDIM><<<g1, blk>>>(g_vals_p, Wo1, bo1, g_hid_p, HDIM);
    dim3 g2(DIN / 64, SN / 64);
    gemm_kernel<0, HDIM><<<g2, blk>>>(g_hid_p, Wo2, bo2, out, DIN);

    // 4) second tuple element: bias passthrough
    cudaMemcpyAsync(out + (size_t)SN * DIN, bias,
                    (size_t)SN * SN * sizeof(float),
                    cudaMemcpyDeviceToDevice, 0);
}

// round 2
// speedup vs baseline: 2.8383x; 2.8383x over previous
#include <cuda_runtime.h>
#include <math.h>
#include <stdint.h>

#define SN 3072
#define DIN 512
#define NH 16
#define HD_ 64
#define HDIM 1024   // NH * HD_

#define FULLM 0xffffffffu

// -------- scratch (device globals; no allocations allowed) --------
__device__ float g_qh[NH * SN * HD_];   // [H][N][D]
__device__ float g_kh[NH * SN * HD_];
__device__ float g_vh[NH * SN * HD_];
__device__ float g_vals[SN * HDIM];     // [N][H*D]
__device__ float g_hid[SN * HDIM];

// ---------------- tf32 helpers ----------------
__device__ __forceinline__ uint32_t f2tf(float x) {
    uint32_t r;
    asm("cvt.rna.tf32.f32 %0, %1;" : "=r"(r) : "f"(x));
    return r;
}

__device__ __forceinline__ void mma8(float* c, const uint32_t* a, uint32_t b0, uint32_t b1) {
    asm volatile(
        "mma.sync.aligned.m16n8k8.row.col.f32.tf32.tf32.f32 "
        "{%0,%1,%2,%3},{%4,%5,%6,%7},{%8,%9},{%0,%1,%2,%3};"
        : "+f"(c[0]), "+f"(c[1]), "+f"(c[2]), "+f"(c[3])
        : "r"(a[0]), "r"(a[1]), "r"(a[2]), "r"(a[3]), "r"(b0), "r"(b1));
}

__device__ __forceinline__ float mish_f(float x) {
    float sp = (x > 20.f) ? x : log1pf(__expf(x));
    return x * tanhf(sp);
}

// ============================================================
// Generic tf32 GEMM: out = epilogue(A[M,K] @ W[NC,K]^T + b)
// BM=128, BN=64, BK=32, 256 threads (8 warps), warp = 16 rows x 64 cols.
// MODE 0: scatter to [H][N][64];  MODE 1: mish -> [N][HDIM];  MODE 2: plain [N][NC]
// ============================================================
#define GPAD 36
#define GEMM_SMEM ((2 * 128 * GPAD + 2 * 64 * GPAD) * 4)

template<int K, int MODE>
__global__ void __launch_bounds__(256, 1) gemm_tf32(
    const float* __restrict__ A, const float* __restrict__ W,
    const float* __restrict__ bvec, float* __restrict__ out, int NC)
{
    extern __shared__ uint32_t smg[];
    uint32_t* AsB = smg;                  // 2 * 128*GPAD
    uint32_t* WsB = smg + 2 * 128 * GPAD; // 2 * 64*GPAD

    const int tid = threadIdx.x, lane = tid & 31, w = tid >> 5;
    const int gq = lane >> 2, tig = lane & 3;
    const int wrow = w * 16;
    const int row0 = blockIdx.y * 128, col0 = blockIdx.x * 64;
    const int lr = tid >> 3, lc4 = (tid & 7) * 4;

    float4 areg[4], wreg[2];
    const int NIT = K / 32;

    auto LDG = [&](int it) {
        const int k0 = it * 32;
        #pragma unroll
        for (int i = 0; i < 4; i++)
            areg[i] = *(const float4*)(A + (size_t)(row0 + i * 32 + lr) * K + k0 + lc4);
        #pragma unroll
        for (int i = 0; i < 2; i++)
            wreg[i] = *(const float4*)(W + (size_t)(col0 + i * 32 + lr) * K + k0 + lc4);
    };
    auto STS = [&](int buf) {
        uint32_t* Ab = AsB + buf * 128 * GPAD;
        uint32_t* Wb = WsB + buf * 64 * GPAD;
        #pragma unroll
        for (int i = 0; i < 4; i++) {
            uint4 u = make_uint4(f2tf(areg[i].x), f2tf(areg[i].y), f2tf(areg[i].z), f2tf(areg[i].w));
            *(uint4*)(Ab + (i * 32 + lr) * GPAD + lc4) = u;
        }
        #pragma unroll
        for (int i = 0; i < 2; i++) {
            uint4 u = make_uint4(f2tf(wreg[i].x), f2tf(wreg[i].y), f2tf(wreg[i].z), f2tf(wreg[i].w));
            *(uint4*)(Wb + (i * 32 + lr) * GPAD + lc4) = u;
        }
    };

    float cf[8][4] = {};
    LDG(0); STS(0); __syncthreads();

    for (int it = 0; it < NIT; it++) {
        if (it + 1 < NIT) LDG(it + 1);
        uint32_t* Ab = AsB + (it & 1) * 128 * GPAD;
        uint32_t* Wb = WsB + (it & 1) * 64 * GPAD;
        #pragma unroll
        for (int kk = 0; kk < 4; kk++) {
            uint32_t af[4];
            af[0] = Ab[(wrow + gq) * GPAD + kk * 8 + tig];
            af[1] = Ab[(wrow + gq + 8) * GPAD + kk * 8 + tig];
            af[2] = Ab[(wrow + gq) * GPAD + kk * 8 + tig + 4];
            af[3] = Ab[(wrow + gq + 8) * GPAD + kk * 8 + tig + 4];
            #pragma unroll
            for (int n = 0; n < 8; n++) {
                uint32_t b0 = Wb[(n * 8 + gq) * GPAD + kk * 8 + tig];
                uint32_t b1 = Wb[(n * 8 + gq) * GPAD + kk * 8 + tig + 4];
                mma8(cf[n], af, b0, b1);
            }
        }
        if (it + 1 < NIT) STS((it + 1) & 1);
        __syncthreads();
    }

    const int mr0 = row0 + wrow + gq, mr1 = mr0 + 8;
    #pragma unroll
    for (int n = 0; n < 8; n++) {
        int cg = col0 + n * 8 + tig * 2;
        float b0v = bvec[cg], b1v = bvec[cg + 1];
        float v00 = cf[n][0] + b0v, v01 = cf[n][1] + b1v;
        float v10 = cf[n][2] + b0v, v11 = cf[n][3] + b1v;
        if (MODE == 0) {
            int h = cg >> 6, d = cg & 63;
            *(float2*)(out + ((size_t)h * SN + mr0) * HD_ + d) = make_float2(v00, v01);
            *(float2*)(out + ((size_t)h * SN + mr1) * HD_ + d) = make_float2(v10, v11);
        } else if (MODE == 1) {
            *(float2*)(out + (size_t)mr0 * HDIM + cg) = make_float2(mish_f(v00), mish_f(v01));
            *(float2*)(out + (size_t)mr1 * HDIM + cg) = make_float2(mish_f(v10), mish_f(v11));
        } else {
            *(float2*)(out + (size_t)mr0 * NC + cg) = make_float2(v00, v01);
            *(float2*)(out + (size_t)mr1 * NC + cg) = make_float2(v10, v11);
        }
    }
}

// ============================================================
// Flash attention, tf32 mma. CTA = (head, 128 Q rows), 8 warps.
// Warp w owns rows [w*16, w*16+16), all 64 key cols per block.
// ============================================================
#define KPAD 68
#define VPAD 72
#define PPAD 68
#define ATTN_SMEM ((64 * KPAD + 64 * VPAD + 128 * PPAD) * 4)

__global__ void __launch_bounds__(256, 1) attn_mma(
    const float* __restrict__ bias, const int* __restrict__ mask)
{
    extern __shared__ uint32_t sma[];
    uint32_t* Ks = sma;               // [64][KPAD]  (K rows x d)
    uint32_t* Vs = Ks + 64 * KPAD;    // [64][VPAD]  (K rows x d)
    uint32_t* Ps = Vs + 64 * VPAD;    // [128][PPAD]

    const int h = blockIdx.x, q0 = blockIdx.y * 128;
    const int tid = threadIdx.x, lane = tid & 31, w = tid >> 5;
    const int gq = lane >> 2, tig = lane & 3;
    const int wrow = w * 16;
    const int r0 = wrow + gq, r1 = r0 + 8;

    const float* qp    = g_qh + (size_t)h * SN * HD_ + (size_t)q0 * HD_;
    const float* kbase = g_kh + (size_t)h * SN * HD_;
    const float* vbase = g_vh + (size_t)h * SN * HD_;

    // Q fragments in registers for the whole kernel
    uint32_t qf[8][4];
    #pragma unroll
    for (int kk = 0; kk < 8; kk++) {
        qf[kk][0] = f2tf(qp[r0 * HD_ + kk * 8 + tig]);
        qf[kk][1] = f2tf(qp[r1 * HD_ + kk * 8 + tig]);
        qf[kk][2] = f2tf(qp[r0 * HD_ + kk * 8 + tig + 4]);
        qf[kk][3] = f2tf(qp[r1 * HD_ + kk * 8 + tig + 4]);
    }

    float of[8][4] = {};
    float m0 = -INFINITY, m1 = -INFINITY, l0 = 0.f, l1 = 0.f;

    const int lr = tid >> 4, lc4 = (tid & 15) * 4;
    float4 kreg[4], vreg[4];
    auto LDGKV = [&](int jb) {
        const int k0 = jb * 64;
        #pragma unroll
        for (int i = 0; i < 4; i++) {
            kreg[i] = *(const float4*)(kbase + (size_t)(k0 + i * 16 + lr) * HD_ + lc4);
            vreg[i] = *(const float4*)(vbase + (size_t)(k0 + i * 16 + lr) * HD_ + lc4);
        }
    };
    LDGKV(0);

    for (int jb = 0; jb < SN / 64; jb++) {
        // stage K/V into smem (tf32)
        #pragma unroll
        for (int i = 0; i < 4; i++) {
            int r = i * 16 + lr;
            *(uint4*)(Ks + r * KPAD + lc4) =
                make_uint4(f2tf(kreg[i].x), f2tf(kreg[i].y), f2tf(kreg[i].z), f2tf(kreg[i].w));
            *(uint4*)(Vs + r * VPAD + lc4) =
                make_uint4(f2tf(vreg[i].x), f2tf(vreg[i].y), f2tf(vreg[i].z), f2tf(vreg[i].w));
        }
        __syncthreads();

        // S = Q K^T  (m16 x n64 x k64 per warp)
        float sf[8][4] = {};
        #pragma unroll
        for (int kk = 0; kk < 8; kk++) {
            #pragma unroll
            for (int n = 0; n < 8; n++) {
                uint32_t b0 = Ks[(n * 8 + gq) * KPAD + kk * 8 + tig];
                uint32_t b1 = Ks[(n * 8 + gq) * KPAD + kk * 8 + tig + 4];
                mma8(sf[n], qf[kk], b0, b1);
            }
        }

        if (jb + 1 < SN / 64) LDGKV(jb + 1);   // prefetch next block

        const int k0 = jb * 64;
        const size_t br0 = (size_t)(q0 + r0) * SN + k0;
        const size_t br1 = (size_t)(q0 + r1) * SN + k0;
        float mx0 = -INFINITY, mx1 = -INFINITY;
        #pragma unroll
        for (int n = 0; n < 8; n++) {
            int c = n * 8 + tig * 2;
            float2 bv0 = *(const float2*)(bias + br0 + c);
            float2 bv1 = *(const float2*)(bias + br1 + c);
            int2   mv0 = *(const int2*)(mask + br0 + c);
            int2   mv1 = *(const int2*)(mask + br1 + c);
            sf[n][0] = mv0.x ? fmaf(sf[n][0], 0.125f, bv0.x) : -9e15f;
            sf[n][1] = mv0.y ? fmaf(sf[n][1], 0.125f, bv0.y) : -9e15f;
            sf[n][2] = mv1.x ? fmaf(sf[n][2], 0.125f, bv1.x) : -9e15f;
            sf[n][3] = mv1.y ? fmaf(sf[n][3], 0.125f, bv1.y) : -9e15f;
            mx0 = fmaxf(mx0, fmaxf(sf[n][0], sf[n][1]));
            mx1 = fmaxf(mx1, fmaxf(sf[n][2], sf[n][3]));
        }
        mx0 = fmaxf(mx0, __shfl_xor_sync(FULLM, mx0, 1));
        mx0 = fmaxf(mx0, __shfl_xor_sync(FULLM, mx0, 2));
        mx1 = fmaxf(mx1, __shfl_xor_sync(FULLM, mx1, 1));
        mx1 = fmaxf(mx1, __shfl_xor_sync(FULLM, mx1, 2));

        float mn0 = fmaxf(m0, mx0), mn1 = fmaxf(m1, mx1);
        float cr0 = __expf(m0 - mn0), cr1 = __expf(m1 - mn1);
        float s0 = 0.f, s1 = 0.f;
        #pragma unroll
        for (int n = 0; n < 8; n++) {
            float p0 = __expf(sf[n][0] - mn0);
            float p1 = __expf(sf[n][1] - mn0);
            float p2 = __expf(sf[n][2] - mn1);
            float p3 = __expf(sf[n][3] - mn1);
            s0 += p0 + p1; s1 += p2 + p3;
            int c = n * 8 + tig * 2;
            *(uint2*)(Ps + r0 * PPAD + c) = make_uint2(f2tf(p0), f2tf(p1));
            *(uint2*)(Ps + r1 * PPAD + c) = make_uint2(f2tf(p2), f2tf(p3));
        }
        s0 += __shfl_xor_sync(FULLM, s0, 1); s0 += __shfl_xor_sync(FULLM, s0, 2);
        s1 += __shfl_xor_sync(FULLM, s1, 1); s1 += __shfl_xor_sync(FULLM, s1, 2);
        l0 = l0 * cr0 + s0; l1 = l1 * cr1 + s1;
        m0 = mn0; m1 = mn1;
        #pragma unroll
        for (int n = 0; n < 8; n++) {
            of[n][0] *= cr0; of[n][1] *= cr0; of[n][2] *= cr1; of[n][3] *= cr1;
        }
        __syncthreads();

        // O += P V  (m16 x n64 x k64 per warp)
        #pragma unroll
        for (int kk = 0; kk < 8; kk++) {
            uint32_t pa[4];
            pa[0] = Ps[(wrow + gq) * PPAD + kk * 8 + tig];
            pa[1] = Ps[(wrow + gq + 8) * PPAD + kk * 8 + tig];
            pa[2] = Ps[(wrow + gq) * PPAD + kk * 8 + tig + 4];
            pa[3] = Ps[(wrow + gq + 8) * PPAD + kk * 8 + tig + 4];
            #pragma unroll
            for (int n = 0; n < 8; n++) {
                uint32_t b0 = Vs[(kk * 8 + tig) * VPAD + n * 8 + gq];
                uint32_t b1 = Vs[(kk * 8 + tig + 4) * VPAD + n * 8 + gq];
                mma8(of[n], pa, b0, b1);
            }
        }
        __syncthreads();
    }

    const float inv0 = 1.f / l0, inv1 = 1.f / l1;
    #pragma unroll
    for (int n = 0; n < 8; n++) {
        int c = h * HD_ + n * 8 + tig * 2;
        *(float2*)(g_vals + (size_t)(q0 + r0) * HDIM + c) = make_float2(of[n][0] * inv0, of[n][1] * inv0);
        *(float2*)(g_vals + (size_t)(q0 + r1) * HDIM + c) = make_float2(of[n][2] * inv1, of[n][3] * inv1);
    }
}

// ============================================================
extern "C" void kernel_launch(void* const* d_in, const int* in_sizes, int n_in,
                              void* d_out, int out_size) {
    const float* q    = (const float*)d_in[0];
    const float* k    = (const float*)d_in[1];
    const float* v    = (const float*)d_in[2];
    const float* bias = (const float*)d_in[3];
    const int*   mask = (const int*)d_in[4];
    const float* Wq   = (const float*)d_in[5];
    const float* bq   = (const float*)d_in[6];
    const float* Wk   = (const float*)d_in[7];
    const float* bk   = (const float*)d_in[8];
    const float* Wv   = (const float*)d_in[9];
    const float* bv   = (const float*)d_in[10];
    const float* Wo1  = (const float*)d_in[11];
    const float* bo1  = (const float*)d_in[12];
    const float* Wo2  = (const float*)d_in[13];
    const float* bo2  = (const float*)d_in[14];
    float* out = (float*)d_out;

    float *g_qh_p, *g_kh_p, *g_vh_p, *g_vals_p, *g_hid_p;
    cudaGetSymbolAddress((void**)&g_qh_p,  g_qh);
    cudaGetSymbolAddress((void**)&g_kh_p,  g_kh);
    cudaGetSymbolAddress((void**)&g_vh_p,  g_vh);
    cudaGetSymbolAddress((void**)&g_vals_p, g_vals);
    cudaGetSymbolAddress((void**)&g_hid_p, g_hid);

    cudaFuncSetAttribute(gemm_tf32<DIN, 0>,  cudaFuncAttributeMaxDynamicSharedMemorySize, GEMM_SMEM);
    cudaFuncSetAttribute(gemm_tf32<HDIM, 1>, cudaFuncAttributeMaxDynamicSharedMemorySize, GEMM_SMEM);
    cudaFuncSetAttribute(gemm_tf32<HDIM, 2>, cudaFuncAttributeMaxDynamicSharedMemorySize, GEMM_SMEM);
    cudaFuncSetAttribute(attn_mma, cudaFuncAttributeMaxDynamicSharedMemorySize, ATTN_SMEM);

    dim3 blk(256);

    // 1) projections: [3072,512] @ [1024,512]^T -> split heads [H][N][64]
    dim3 gp(HDIM / 64, SN / 128);
    gemm_tf32<DIN, 0><<<gp, blk, GEMM_SMEM>>>(q, Wq, bq, g_qh_p, HDIM);
    gemm_tf32<DIN, 0><<<gp, blk, GEMM_SMEM>>>(k, Wk, bk, g_kh_p, HDIM);
    gemm_tf32<DIN, 0><<<gp, blk, GEMM_SMEM>>>(v, Wv, bv, g_vh_p, HDIM);

    // 2) flash attention
    dim3 ga(NH, SN / 128);
    attn_mma<<<ga, blk, ATTN_SMEM>>>(bias, mask);

    // 3) MLP: mish(vals @ Wo1^T + bo1) @ Wo2^T + bo2
    dim3 g1(HDIM / 64, SN / 128);
    gemm_tf32<HDIM, 1><<<g1, blk, GEMM_SMEM>>>(g_vals_p, Wo1, bo1, g_hid_p, HDIM);
    dim3 g2(DIN / 64, SN / 128);
    gemm_tf32<HDIM, 2><<<g2, blk, GEMM_SMEM>>>(g_hid_p, Wo2, bo2, out, DIN);

    // 4) second tuple element: bias passthrough
    cudaMemcpyAsync(out + (size_t)SN * DIN, bias,
                    (size_t)SN * SN * sizeof(float),
                    cudaMemcpyDeviceToDevice, 0);
}